// round 2
// baseline (speedup 1.0000x reference)
#include <cuda_runtime.h>
#include <math.h>

// Problem constants
#define NN0 4096
#define NN1 1024
#define FIN 8
#define HH 64
#define FF 67
#define FPAD 68
#define LLAT 32

// Scratch (device globals: no allocation allowed)
__device__ float    g_xf0[NN0 * FPAD];   // encoder out || pos  (conv0 input features)
__device__ float    g_out0[NN0 * HH];    // conv0 accumulation
__device__ float    g_h0s[NN0 * HH];     // sin(0.01*conv0)
__device__ unsigned g_maxkey[NN0 * HH];  // monotone-key max pool
__device__ float    g_xf1[NN1 * FPAD];   // pooled feats || pool_pos1
__device__ float    g_out1[NN1 * HH];    // conv1 accumulation

__device__ __forceinline__ unsigned fkey(float f) {
    int i = __float_as_int(f);
    return (i < 0) ? ~(unsigned)i : ((unsigned)i | 0x80000000u);
}
__device__ __forceinline__ float funkey(unsigned u) {
    int i = (u & 0x80000000u) ? (int)(u & 0x7fffffffu) : ~(int)u;
    return __int_as_float(i);
}

// ---------------- encode: g_xf0 = [sin(0.01*(x@W+b)) || pos], init out0 with bias
__global__ void k_encode(const float* __restrict__ x, const float* __restrict__ pos,
                         const float* __restrict__ w, const float* __restrict__ b,
                         const float* __restrict__ bias0) {
    int n = blockIdx.x, t = threadIdx.x;  // block = 64
    float acc = b[t];
#pragma unroll
    for (int f = 0; f < FIN; f++) acc = fmaf(x[n * FIN + f], w[f * HH + t], acc);
    g_xf0[n * FPAD + t] = sinf(0.01f * acc);
    if (t < 3)  g_xf0[n * FPAD + 64 + t] = pos[n * 3 + t];
    if (t == 3) g_xf0[n * FPAD + 67] = 0.f;
    g_out0[n * HH + t] = bias0[t];
}

// ---------------- the kernel-conv: warp per edge -------------------------------
__global__ __launch_bounds__(256, 2)
void k_conv(const float* __restrict__ xf, const int* __restrict__ ei,
            int Eorig, int Etot, const float* __restrict__ pos,
            const float* __restrict__ w0, const float* __restrict__ b0,
            const float* __restrict__ w1, const float* __restrict__ b1,
            const float* __restrict__ w2, const float* __restrict__ b2,
            float* __restrict__ out) {
    __shared__ float4 w1s[HH * 16];       // w1 rows as float4 (k groups of 4)
    __shared__ float  w2s[HH * FF];
    __shared__ float  w0s[3 * HH];        // 0.1 * w0[0:3,:]
    __shared__ float  dws[HH];            // 0.1 * w0[3,:]
    __shared__ float  b0s[HH];            // 0.1 * b0
    __shared__ float  b1s[HH];
    __shared__ float  b2s[FF];
    __shared__ float  xjs[8][FPAD];
    __shared__ float  ts[8][HH];
    __shared__ float  bas[8][HH];

    int tid = threadIdx.x;
    for (int i = tid; i < HH * 16; i += 256) w1s[i] = ((const float4*)w1)[i];
    for (int i = tid; i < HH * FF; i += 256) w2s[i] = w2[i];
    if (tid < 192) w0s[tid] = 0.1f * w0[tid];
    else           dws[tid - 192] = 0.1f * w0[tid];  // tid in [192,256) -> row 3
    if (tid < HH) { b0s[tid] = 0.1f * b0[tid]; b1s[tid] = b1[tid]; }
    if (tid < FF)  b2s[tid] = b2[tid];
    __syncthreads();

    int w = tid >> 5, lane = tid & 31;
    int e = blockIdx.x * 8 + w;
    if (e >= Etot) return;

    int src, dst;
    if (e < Eorig) { src = ei[e]; dst = ei[Eorig + e]; }
    else           { src = dst = e - Eorig; }

    float rx = pos[dst * 3 + 0] - pos[src * 3 + 0];
    float ry = pos[dst * 3 + 1] - pos[src * 3 + 1];
    float rz = pos[dst * 3 + 2] - pos[src * 3 + 2];
    float f0 = 0.f, f1 = 0.f, f2 = 0.f;
    if (!(rx == 0.f && ry == 0.f && rz == 0.f)) {
        float rho = sqrtf(rx * rx + ry * ry + rz * rz);
        const float INV_PI = 0.31830988618379067f;
        f0 = rho;
        f1 = atan2f(ry, rx) * INV_PI;
        f2 = asinf(fminf(fmaxf(rz / rho, -1.f), 1.f)) * INV_PI;
    }

    // gather x_j (includes pad col 67 == 0)
    xjs[w][lane]       = xf[src * FPAD + lane];
    xjs[w][lane + 32]  = xf[src * FPAD + lane + 32];
    if (lane < 4) xjs[w][lane + 64] = xf[src * FPAD + lane + 64];
    // bases (already scaled by 0.1): lane owns h = lane, lane+32
    int ha = lane, hb = lane + 32;
    bas[w][ha] = fmaf(f0, w0s[ha], fmaf(f1, w0s[64 + ha], fmaf(f2, w0s[128 + ha], b0s[ha])));
    bas[w][hb] = fmaf(f0, w0s[hb], fmaf(f1, w0s[64 + hb], fmaf(f2, w0s[128 + hb], b0s[hb])));
    __syncwarp();

    // t[h] = w2[h,:] . x_j ; xb2 = b2 . x_j (redundant per lane, cheap)
    float t0 = 0.f, t1 = 0.f, xb2 = 0.f;
#pragma unroll
    for (int f = 0; f < FF; f++) {
        float xv = xjs[w][f];
        t0  = fmaf(w2s[ha * FF + f], xv, t0);
        t1  = fmaf(w2s[hb * FF + f], xv, t1);
        xb2 = fmaf(b2s[f], xv, xb2);
    }
    ts[w][ha] = t0; ts[w][hb] = t1;
    __syncwarp();

    // main: lane handles channels c = lane and lane+32 sequentially
#pragma unroll 1
    for (int cp = 0; cp < 2; cp++) {
        float cF = (float)(lane + 32 * cp);
        float h0r[HH];
#pragma unroll
        for (int h = 0; h < HH; h++)
            h0r[h] = __sinf(fmaf(cF, dws[h], bas[w][h]));

        float msg = xb2;
#pragma unroll 1
        for (int kt = 0; kt < 16; kt++) {
            float a0 = b1s[4 * kt + 0], a1 = b1s[4 * kt + 1];
            float a2 = b1s[4 * kt + 2], a3 = b1s[4 * kt + 3];
#pragma unroll
            for (int h = 0; h < HH; h++) {
                float4 wv = w1s[h * 16 + kt];
                a0 = fmaf(h0r[h], wv.x, a0);
                a1 = fmaf(h0r[h], wv.y, a1);
                a2 = fmaf(h0r[h], wv.z, a2);
                a3 = fmaf(h0r[h], wv.w, a3);
            }
            msg = fmaf(__sinf(0.1f * a0), ts[w][4 * kt + 0], msg);
            msg = fmaf(__sinf(0.1f * a1), ts[w][4 * kt + 1], msg);
            msg = fmaf(__sinf(0.1f * a2), ts[w][4 * kt + 2], msg);
            msg = fmaf(__sinf(0.1f * a3), ts[w][4 * kt + 3], msg);
        }
        atomicAdd(&out[dst * HH + lane + 32 * cp], msg);
    }
}

// ---------------- post conv0: sin + init max keys (self-loop = init value)
__global__ void k_post0() {
    int i = blockIdx.x * 256 + threadIdx.x;  // NN0*HH total
    float v = sinf(0.01f * g_out0[i]);
    g_h0s[i] = v;
    g_maxkey[i] = fkey(v);
}

// ---------------- scatter-max over original edges
__global__ void k_smax(const int* __restrict__ ei, int E) {
    int idx = blockIdx.x * 256 + threadIdx.x;
    if (idx >= E * HH) return;
    int e = idx >> 6, c = idx & 63;
    int src = ei[e], dst = ei[E + e];
    atomicMax(&g_maxkey[dst * HH + c], fkey(g_h0s[src * HH + c]));
}

// ---------------- build conv1 input + init out1 with bias
__global__ void k_build1(const int* __restrict__ keep, const float* __restrict__ ppos,
                         const float* __restrict__ bias1) {
    int i = blockIdx.x, t = threadIdx.x;  // block = 64
    int n = keep[i];
    g_xf1[i * FPAD + t] = funkey(g_maxkey[n * HH + t]);
    if (t < 3)  g_xf1[i * FPAD + 64 + t] = ppos[i * 3 + t];
    if (t == 3) g_xf1[i * FPAD + 67] = 0.f;
    g_out1[i * HH + t] = bias1[t];
}

// ---------------- decode
__global__ void k_decode(const float* __restrict__ w, const float* __restrict__ b,
                         float* __restrict__ out) {
    __shared__ float hs[HH];
    int i = blockIdx.x, t = threadIdx.x;  // block = 64
    hs[t] = sinf(0.01f * g_out1[i * HH + t]);
    __syncthreads();
    if (t < LLAT) {
        float acc = b[t];
#pragma unroll
        for (int c = 0; c < HH; c++) acc = fmaf(hs[c], w[c * LLAT + t], acc);
        out[i * LLAT + t] = sinf(0.01f * acc);
    }
}

extern "C" void kernel_launch(void* const* d_in, const int* in_sizes, int n_in,
                              void* d_out, int out_size) {
    const float* x = (const float*)d_in[0];
    const float* pos;
    const int*   ei;
    int szEi;
    if (in_sizes[1] == NN0 * 3) {  // dict order: x, pos, edge_index
        pos = (const float*)d_in[1]; ei = (const int*)d_in[2]; szEi = in_sizes[2];
    } else {                       // signature order: x, edge_index, pos
        ei = (const int*)d_in[1]; pos = (const float*)d_in[2]; szEi = in_sizes[1];
    }
    const int*   ei1    = (const int*)d_in[3];
    const float* ppos   = (const float*)d_in[4];
    const int*   keep   = (const int*)d_in[5];
    const float* lin0_w = (const float*)d_in[6];
    const float* lin0_b = (const float*)d_in[7];
    const float* lin1_w = (const float*)d_in[8];
    const float* lin1_b = (const float*)d_in[9];
    const float* c0w0 = (const float*)d_in[10], *c0b0 = (const float*)d_in[11];
    const float* c0w1 = (const float*)d_in[12], *c0b1 = (const float*)d_in[13];
    const float* c0w2 = (const float*)d_in[14], *c0b2 = (const float*)d_in[15];
    const float* c0bias = (const float*)d_in[16];
    const float* c1w0 = (const float*)d_in[17], *c1b0 = (const float*)d_in[18];
    const float* c1w1 = (const float*)d_in[19], *c1b1 = (const float*)d_in[20];
    const float* c1w2 = (const float*)d_in[21], *c1b2 = (const float*)d_in[22];
    const float* c1bias = (const float*)d_in[23];

    int E0 = szEi / 2;            // 16384
    int E1 = in_sizes[3] / 2;     // 8192
    int E0t = E0 + NN0;           // + self loops
    int E1t = E1 + NN1;

    float *xf0, *out0, *xf1, *out1;
    cudaGetSymbolAddress((void**)&xf0,  g_xf0);
    cudaGetSymbolAddress((void**)&out0, g_out0);
    cudaGetSymbolAddress((void**)&xf1,  g_xf1);
    cudaGetSymbolAddress((void**)&out1, g_out1);

    k_encode<<<NN0, 64>>>(x, pos, lin0_w, lin0_b, c0bias);
    k_conv<<<(E0t + 7) / 8, 256>>>(xf0, ei, E0, E0t, pos,
                                   c0w0, c0b0, c0w1, c0b1, c0w2, c0b2, out0);
    k_post0<<<(NN0 * HH) / 256, 256>>>();
    k_smax<<<(E0 * HH + 255) / 256, 256>>>(ei, E0);
    k_build1<<<NN1, 64>>>(keep, ppos, c1bias);
    k_conv<<<(E1t + 7) / 8, 256>>>(xf1, ei1, E1, E1t, ppos,
                                   c1w0, c1b0, c1w1, c1b1, c1w2, c1b2, out1);
    k_decode<<<NN1, 64>>>(lin1_w, lin1_b, (float*)d_out);
}